// round 9
// baseline (speedup 1.0000x reference)
#include <cuda_runtime.h>
#include <cuda_fp16.h>
#include <math.h>
#include <stdint.h>

#define N_NODES 100000
#define D 128
#define FAN_IN 384
#define E_MAX 1600000
#define SCAN_BLOCKS ((N_NODES + 255) / 256)   // 391

// ---- scratch (__device__ globals; no allocations allowed) ----
__device__ __align__(16) __half g_featH[N_NODES * D];
__device__ __align__(16) __half g_h1H[N_NODES * D];
__device__ __align__(16) __half g_h2H[N_NODES * D];
__device__ __align__(16) __half g_WH[FAN_IN * D];    // W fp16, row-major [128][384]
__device__ float g_norm[N_NODES];
__device__ int   g_deg[N_NODES];          // zeroed at end of each run (and by static init)
__device__ int   g_row[N_NODES + 1];
__device__ int   g_cursor[N_NODES];
__device__ int   g_csr[E_MAX];
__device__ volatile int g_agg[SCAN_BLOCKS];    // block sums, value+1 ("0" = not ready)
__device__ volatile int g_boffp[SCAN_BLOCKS];  // block offsets, value+1

// ---------------------------------------------------------------------------
// inline int64 probe: reference guarantees dst[0..N-1]==arange(N).
// int64 LE as int32 words: [0,0,1,0,2,0,...]; int32: [0,1,2,...]
__device__ __forceinline__ int probe_is64(const int* dst32) {
    return (dst32[1] == 0 && dst32[2] == 1 && dst32[4] == 2) ? 1 : 0;
}
__device__ __forceinline__ int load_idx(const int* p, int e, int is64) {
    return is64 ? p[2 * e] : p[e];
}

// launch 1: degree histogram (g_deg pre-zeroed by previous run / static init)
__global__ void deg_kernel(const int* __restrict__ dst32, int E) {
    int is64 = probe_is64(dst32);
    int e = blockIdx.x * blockDim.x + threadIdx.x;
    if (e < E) atomicAdd(&g_deg[load_idx(dst32, e, is64)], 1);
}

// launch 2: fused single-pass scan. 512 threads, grid=SCAN_BLOCKS.
// Per block: scan 256 degrees; publish block sum; block 0 scans all block
// sums centrally; every block spin-waits for its offset, then writes
// row/cursor/norm. All 391 blocks co-resident (cap ~592) -> no deadlock.
__global__ __launch_bounds__(512)
void scan_fused_kernel() {
    __shared__ int sh[512];
    __shared__ int wsum[8];
    __shared__ int sh_total;
    __shared__ int sh_boff;
    int t = threadIdx.x;
    int b = blockIdx.x;
    int lane = t & 31, warp = t >> 5;
    int g = b * 256 + t;                        // valid for t<256
    int v = (t < 256 && g < N_NODES) ? g_deg[g] : 0;

    // warp inclusive scan (warps 0..7 carry data)
    int inc = v;
#pragma unroll
    for (int o = 1; o < 32; o <<= 1) {
        int u = __shfl_up_sync(0xffffffffu, inc, o);
        if (lane >= o) inc += u;
    }
    if (lane == 31 && warp < 8) wsum[warp] = inc;
    __syncthreads();
    if (t < 8) {
        int s = wsum[t];
        int si = s;
#pragma unroll
        for (int o = 1; o < 8; o <<= 1) {
            int u = __shfl_up_sync(0xffu, si, o);
            if (t >= o) si += u;
        }
        wsum[t] = si - s;                       // exclusive warp offset
        if (t == 7) sh_total = si;              // block total
    }
    __syncthreads();

    // publish block aggregate (value+1; the value is the flag)
    if (t == 0) g_agg[b] = sh_total + 1;

    // block 0: central scan of all block aggregates
    if (b == 0) {
        int a = 0;
        if (t < SCAN_BLOCKS) {
            while ((a = g_agg[t]) == 0) { }
            a -= 1;
        }
        sh[t] = a;
        __syncthreads();
        for (int off = 1; off < 512; off <<= 1) {
            int u = (t >= off) ? sh[t - off] : 0;
            __syncthreads();
            sh[t] += u;
            __syncthreads();
        }
        if (t < SCAN_BLOCKS)
            g_boffp[t] = ((t == 0) ? 0 : sh[t - 1]) + 1;
    }

    // all blocks: wait for own offset
    if (t == 0) {
        int bo;
        while ((bo = g_boffp[b]) == 0) { }
        sh_boff = bo - 1;
    }
    __syncthreads();

    if (t < 256 && g < N_NODES) {
        int row = sh_boff + wsum[warp] + inc - v;   // exclusive prefix
        g_row[g] = row;
        g_cursor[g] = row;
        g_norm[g] = rsqrtf((float)v);
        if (g == N_NODES - 1) g_row[N_NODES] = row + v;
    }
}

// launch 3: CSR bucket-fill + feat->fp16 + W->fp16 + state cleanup for next run
__global__ void fill_convert_kernel(const int* __restrict__ src32,
                                    const int* __restrict__ dst32,
                                    const float* __restrict__ feat,
                                    const float* __restrict__ W, int E) {
    int i = blockIdx.x * blockDim.x + threadIdx.x;
    if (i < E) {
        int is64 = probe_is64(dst32);
        int tt = load_idx(dst32, i, is64);
        int s = load_idx(src32, i, is64);
        int pos = atomicAdd(&g_cursor[tt], 1);
        g_csr[pos] = s;
    }
    if (i < N_NODES * D / 2) {
        float2 v = *(const float2*)&feat[i * 2];
        ((__half2*)g_featH)[i] = __floats2half2_rn(v.x, v.y);
    }
    if (i < FAN_IN * D / 2) {
        float2 v = *(const float2*)&W[i * 2];
        ((__half2*)g_WH)[i] = __floats2half2_rn(v.x, v.y);
    }
    // cleanup for next graph replay (these arrays are done being read this run)
    if (i < SCAN_BLOCKS) { g_agg[i] = 0; g_boffp[i] = 0; }
    if (i < N_NODES) g_deg[i] = 0;
}

// ---------------------------------------------------------------------------
// launch 4+5: gather SpMM (fp16 I/O, fp32 accumulate) — measured-best config
__global__ __launch_bounds__(256)
void gather_kernel(const __half* __restrict__ hin, __half* __restrict__ hout) {
    int warp = (blockIdx.x * 256 + threadIdx.x) >> 5;
    int lane = threadIdx.x & 31;
    if (warp >= N_NODES) return;
    int node  = warp;
    int start = g_row[node];
    int end   = g_row[node + 1];

    const uint2* hin2 = (const uint2*)hin;
    float ax = 0.f, ay = 0.f, az = 0.f, aw = 0.f;

    int e = start;
    for (; e + 4 <= end; e += 4) {
        int s0 = g_csr[e],     s1 = g_csr[e + 1];
        int s2 = g_csr[e + 2], s3 = g_csr[e + 3];
        float n0 = g_norm[s0], n1 = g_norm[s1];
        float n2 = g_norm[s2], n3 = g_norm[s3];
        uint2 r0 = __ldg(&hin2[s0 * 32 + lane]);
        uint2 r1 = __ldg(&hin2[s1 * 32 + lane]);
        uint2 r2 = __ldg(&hin2[s2 * 32 + lane]);
        uint2 r3 = __ldg(&hin2[s3 * 32 + lane]);
        float2 a0 = __half22float2(*(__half2*)&r0.x), b0 = __half22float2(*(__half2*)&r0.y);
        float2 a1 = __half22float2(*(__half2*)&r1.x), b1 = __half22float2(*(__half2*)&r1.y);
        float2 a2 = __half22float2(*(__half2*)&r2.x), b2 = __half22float2(*(__half2*)&r2.y);
        float2 a3 = __half22float2(*(__half2*)&r3.x), b3 = __half22float2(*(__half2*)&r3.y);
        ax += a0.x * n0; ay += a0.y * n0; az += b0.x * n0; aw += b0.y * n0;
        ax += a1.x * n1; ay += a1.y * n1; az += b1.x * n1; aw += b1.y * n1;
        ax += a2.x * n2; ay += a2.y * n2; az += b2.x * n2; aw += b2.y * n2;
        ax += a3.x * n3; ay += a3.y * n3; az += b3.x * n3; aw += b3.y * n3;
    }
    for (; e < end; e++) {
        int s0 = g_csr[e];
        float n0 = g_norm[s0];
        uint2 r0 = __ldg(&hin2[s0 * 32 + lane]);
        float2 a0 = __half22float2(*(__half2*)&r0.x), b0 = __half22float2(*(__half2*)&r0.y);
        ax += a0.x * n0; ay += a0.y * n0; az += b0.x * n0; aw += b0.y * n0;
    }

    float nd = g_norm[node];
    __half2 lo = __floats2half2_rn(ax * nd, ay * nd);
    __half2 hi = __floats2half2_rn(az * nd, aw * nd);
    uint2 o;
    o.x = *(uint32_t*)&lo;
    o.y = *(uint32_t*)&hi;
    ((uint2*)hout)[node * 32 + lane] = o;
}

// ---------------------------------------------------------------------------
// launch 6: HMMA fp16 GEMM: out[n][o] = bias[o] + sum_k x[n][k]*W[o][k]
__device__ __forceinline__ uint32_t smem_u32(const void* p) {
    uint32_t a;
    asm("{ .reg .u64 t; cvta.to.shared.u64 t, %1; cvt.u32.u64 %0, t; }"
        : "=r"(a) : "l"(p));
    return a;
}
__device__ __forceinline__ uint32_t sw128(uint32_t off) {
    return off ^ ((off >> 3) & 0x70);
}

__global__ __launch_bounds__(256)
void gemm_hmma_kernel(const float* __restrict__ bias,
                      float* __restrict__ out) {
    __shared__ __align__(128) char smA[128 * 128];
    __shared__ __align__(128) char smB[128 * 128];

    int tid = threadIdx.x;
    int wid = tid >> 5;
    int lane = tid & 31;
    int warp_m = wid >> 2;
    int warp_n = wid & 3;
    int rowBase = blockIdx.x * 128;

    uint32_t sa = smem_u32(smA);
    uint32_t sb = smem_u32(smB);

    float acc[4][4][4];
#pragma unroll
    for (int i = 0; i < 4; i++)
#pragma unroll
        for (int j = 0; j < 4; j++)
#pragma unroll
            for (int q = 0; q < 4; q++) acc[i][j][q] = 0.f;

    for (int ch = 0; ch < 6; ch++) {
        const __half* baseH = (ch < 2) ? g_featH : ((ch < 4) ? g_h1H : g_h2H);
        int koff = (ch & 1) * 64;
#pragma unroll
        for (int it = 0; it < 4; it++) {
            int idx = tid + it * 256;
            int r = idx >> 3;
            int j = idx & 7;
            int grow = rowBase + r;
            uint4 v = make_uint4(0, 0, 0, 0);
            if (grow < N_NODES)
                v = *(const uint4*)&baseH[grow * D + koff + j * 8];
            *(uint4*)(smA + sw128((uint32_t)(r * 128 + j * 16))) = v;
        }
#pragma unroll
        for (int it = 0; it < 4; it++) {
            int idx = tid + it * 256;
            int r = idx >> 3;
            int j = idx & 7;
            uint4 v = *(const uint4*)&g_WH[r * FAN_IN + ch * 64 + j * 8];
            *(uint4*)(smB + sw128((uint32_t)(r * 128 + j * 16))) = v;
        }
        __syncthreads();

#pragma unroll
        for (int kk = 0; kk < 4; kk++) {
            uint32_t afrag[4][4];
#pragma unroll
            for (int mi = 0; mi < 4; mi++) {
                int r = warp_m * 64 + mi * 16 + (lane & 15);
                uint32_t addr = sa + sw128((uint32_t)(r * 128 + kk * 32 + (lane >> 4) * 16));
                asm volatile(
                    "ldmatrix.sync.aligned.m8n8.x4.shared.b16 {%0,%1,%2,%3}, [%4];"
                    : "=r"(afrag[mi][0]), "=r"(afrag[mi][1]),
                      "=r"(afrag[mi][2]), "=r"(afrag[mi][3])
                    : "r"(addr));
            }
            uint32_t bfrag[4][2];
#pragma unroll
            for (int ni = 0; ni < 4; ni++) {
                int nr = warp_n * 32 + ni * 8 + (lane & 7);
                uint32_t addr = sb + sw128((uint32_t)(nr * 128 + kk * 32 + ((lane >> 3) & 1) * 16));
                asm volatile(
                    "ldmatrix.sync.aligned.m8n8.x2.shared.b16 {%0,%1}, [%2];"
                    : "=r"(bfrag[ni][0]), "=r"(bfrag[ni][1])
                    : "r"(addr));
            }
#pragma unroll
            for (int mi = 0; mi < 4; mi++)
#pragma unroll
                for (int ni = 0; ni < 4; ni++) {
                    asm volatile(
                        "mma.sync.aligned.m16n8k16.row.col.f32.f16.f16.f32 "
                        "{%0,%1,%2,%3}, {%4,%5,%6,%7}, {%8,%9}, {%0,%1,%2,%3};"
                        : "+f"(acc[mi][ni][0]), "+f"(acc[mi][ni][1]),
                          "+f"(acc[mi][ni][2]), "+f"(acc[mi][ni][3])
                        : "r"(afrag[mi][0]), "r"(afrag[mi][1]),
                          "r"(afrag[mi][2]), "r"(afrag[mi][3]),
                          "r"(bfrag[ni][0]), "r"(bfrag[ni][1]));
                }
        }
        __syncthreads();
    }

#pragma unroll
    for (int mi = 0; mi < 4; mi++) {
        int r0 = rowBase + warp_m * 64 + mi * 16 + (lane >> 2);
#pragma unroll
        for (int ni = 0; ni < 4; ni++) {
            int col = warp_n * 32 + ni * 8 + (lane & 3) * 2;
            float b0 = __ldg(&bias[col]);
            float b1 = __ldg(&bias[col + 1]);
            if (r0 < N_NODES) {
                *(float2*)&out[r0 * D + col] =
                    make_float2(acc[mi][ni][0] + b0, acc[mi][ni][1] + b1);
            }
            if (r0 + 8 < N_NODES) {
                *(float2*)&out[(r0 + 8) * D + col] =
                    make_float2(acc[mi][ni][2] + b0, acc[mi][ni][3] + b1);
            }
        }
    }
}

// ---------------------------------------------------------------------------
extern "C" void kernel_launch(void* const* d_in, const int* in_sizes, int n_in,
                              void* d_out, int out_size) {
    const float* feat = (const float*)d_in[0];
    const int*   src  = (const int*)d_in[1];
    const int*   dst  = (const int*)d_in[2];
    const float* W    = (const float*)d_in[3];
    const float* bias = (const float*)d_in[4];
    float* out = (float*)d_out;

    const int E = in_sizes[1];

    __half* featH; cudaGetSymbolAddress((void**)&featH, g_featH);
    __half* h1H;   cudaGetSymbolAddress((void**)&h1H,   g_h1H);
    __half* h2H;   cudaGetSymbolAddress((void**)&h2H,   g_h2H);

    // 1. degrees (g_deg arrives zeroed; cleaned at end of each run)
    deg_kernel<<<(E + 255) / 256, 256>>>(dst, E);
    // 2. fused single-pass scan
    scan_fused_kernel<<<SCAN_BLOCKS, 512>>>();
    // 3. CSR fill + converts + state cleanup
    fill_convert_kernel<<<(N_NODES * D / 2 + 255) / 256, 256>>>(src, dst, feat, W, E);

    // 4-5. two SpMM hops (launch 4 = ncu's profiled slot)
    int gblocks = (N_NODES * 32 + 255) / 256;
    gather_kernel<<<gblocks, 256>>>(featH, h1H);
    gather_kernel<<<gblocks, 256>>>(h1H, h2H);

    // 6. fused concat + linear on tensor cores
    int gemmBlocks = (N_NODES + 127) / 128;
    gemm_hmma_kernel<<<gemmBlocks, 256>>>(bias, out);
}

// round 10
// speedup vs baseline: 1.3681x; 1.3681x over previous
#include <cuda_runtime.h>
#include <cuda_fp16.h>
#include <math.h>
#include <stdint.h>

#define N_NODES 100000
#define D 128
#define FAN_IN 384
#define E_MAX 1600000
#define SCAN_BLOCKS ((N_NODES + 255) / 256)   // 391

// ---- scratch (__device__ globals; no allocations allowed) ----
__device__ __align__(16) __half g_featH[N_NODES * D];  // raw feat fp16 (GEMM)
__device__ __align__(16) __half g_p0[N_NODES * D];     // feat*norm (gather1 input)
__device__ __align__(16) __half g_p1[N_NODES * D];     // norm^2*q1 (gather2 input)
__device__ __align__(16) __half g_h1H[N_NODES * D];    // h1 (GEMM)
__device__ __align__(16) __half g_h2H[N_NODES * D];    // h2 (GEMM)
__device__ __align__(16) __half g_WH[FAN_IN * D];      // W fp16 [128][384]
__device__ float g_norm[N_NODES];
__device__ int   g_deg[N_NODES];            // zeroed at end of each run (+ static init)
__device__ int   g_row[N_NODES + 1];
__device__ int   g_cursor[N_NODES];
__device__ __align__(16) int g_csr[E_MAX];
__device__ volatile int g_agg[SCAN_BLOCKS];
__device__ volatile int g_boffp[SCAN_BLOCKS];

// ---------------------------------------------------------------------------
__device__ __forceinline__ int probe_is64(const int* dst32) {
    return (dst32[1] == 0 && dst32[2] == 1 && dst32[4] == 2) ? 1 : 0;
}
__device__ __forceinline__ int load_idx(const int* p, int e, int is64) {
    return is64 ? p[2 * e] : p[e];
}

// launch 1: degree histogram
__global__ void deg_kernel(const int* __restrict__ dst32, int E) {
    int is64 = probe_is64(dst32);
    int e = blockIdx.x * blockDim.x + threadIdx.x;
    if (e < E) atomicAdd(&g_deg[load_idx(dst32, e, is64)], 1);
}

// launch 2: fused single-pass scan (391 co-resident blocks, spin handshake)
__global__ __launch_bounds__(512)
void scan_fused_kernel() {
    __shared__ int sh[512];
    __shared__ int wsum[8];
    __shared__ int sh_total;
    __shared__ int sh_boff;
    int t = threadIdx.x;
    int b = blockIdx.x;
    int lane = t & 31, warp = t >> 5;
    int g = b * 256 + t;
    int v = (t < 256 && g < N_NODES) ? g_deg[g] : 0;

    int inc = v;
#pragma unroll
    for (int o = 1; o < 32; o <<= 1) {
        int u = __shfl_up_sync(0xffffffffu, inc, o);
        if (lane >= o) inc += u;
    }
    if (lane == 31 && warp < 8) wsum[warp] = inc;
    __syncthreads();
    if (t < 8) {
        int s = wsum[t];
        int si = s;
#pragma unroll
        for (int o = 1; o < 8; o <<= 1) {
            int u = __shfl_up_sync(0xffu, si, o);
            if (t >= o) si += u;
        }
        wsum[t] = si - s;
        if (t == 7) sh_total = si;
    }
    __syncthreads();

    if (t == 0) g_agg[b] = sh_total + 1;

    if (b == 0) {
        int a = 0;
        if (t < SCAN_BLOCKS) {
            while ((a = g_agg[t]) == 0) { }
            a -= 1;
        }
        sh[t] = a;
        __syncthreads();
        for (int off = 1; off < 512; off <<= 1) {
            int u = (t >= off) ? sh[t - off] : 0;
            __syncthreads();
            sh[t] += u;
            __syncthreads();
        }
        if (t < SCAN_BLOCKS)
            g_boffp[t] = ((t == 0) ? 0 : sh[t - 1]) + 1;
    }

    if (t == 0) {
        int bo;
        while ((bo = g_boffp[b]) == 0) { }
        sh_boff = bo - 1;
    }
    __syncthreads();

    if (t < 256 && g < N_NODES) {
        int row = sh_boff + wsum[warp] + inc - v;
        g_row[g] = row;
        g_cursor[g] = row;
        g_norm[g] = rsqrtf((float)v);
        if (g == N_NODES - 1) g_row[N_NODES] = row + v;
    }
}

// launch 3: CSR fill + featH + p0=feat*norm + WH + cleanup for next replay
__global__ void fill_convert_kernel(const int* __restrict__ src32,
                                    const int* __restrict__ dst32,
                                    const float* __restrict__ feat,
                                    const float* __restrict__ W, int E) {
    int i = blockIdx.x * blockDim.x + threadIdx.x;
    if (i < E) {
        int is64 = probe_is64(dst32);
        int tt = load_idx(dst32, i, is64);
        int s = load_idx(src32, i, is64);
        int pos = atomicAdd(&g_cursor[tt], 1);
        g_csr[pos] = s;
    }
    if (i < N_NODES * D / 2) {
        float nn = g_norm[i >> 6];
        float2 v = *(const float2*)&feat[i * 2];
        ((__half2*)g_featH)[i] = __floats2half2_rn(v.x, v.y);
        ((__half2*)g_p0)[i]    = __floats2half2_rn(v.x * nn, v.y * nn);
    }
    if (i < FAN_IN * D / 2) {
        float2 v = *(const float2*)&W[i * 2];
        ((__half2*)g_WH)[i] = __floats2half2_rn(v.x, v.y);
    }
    if (i < SCAN_BLOCKS) { g_agg[i] = 0; g_boffp[i] = 0; }
    if (i < N_NODES) g_deg[i] = 0;
}

// ---------------------------------------------------------------------------
// gather on prescaled input: q = sum_e pin[csr[e]];
// hout = norm*q (fp16); pout = norm^2*q (fp16) if non-null.
// uint4 broadcast loads for 4 CSR indices at a time.
__global__ __launch_bounds__(256)
void gather_kernel(const __half* __restrict__ pin,
                   __half* __restrict__ hout,
                   __half* __restrict__ pout) {
    int node = (blockIdx.x * 256 + threadIdx.x) >> 5;
    int lane = threadIdx.x & 31;
    if (node >= N_NODES) return;
    int start = g_row[node];
    int end   = g_row[node + 1];

    const uint2* pin2 = (const uint2*)pin;
    float ax = 0.f, ay = 0.f, az = 0.f, aw = 0.f;

    int e = start;
    // scalar head until e is 4-aligned (g_csr is 16B aligned)
    while (e < end && (e & 3)) {
        int s = g_csr[e++];
        uint2 r = __ldg(&pin2[s * 32 + lane]);
        float2 a = __half22float2(*(__half2*)&r.x), b = __half22float2(*(__half2*)&r.y);
        ax += a.x; ay += a.y; az += b.x; aw += b.y;
    }
    // main: 4 edges per iter, one LDG.128 broadcast for indices
    for (; e + 4 <= end; e += 4) {
        uint4 i4 = *(const uint4*)&g_csr[e];
        uint2 r0 = __ldg(&pin2[(int)i4.x * 32 + lane]);
        uint2 r1 = __ldg(&pin2[(int)i4.y * 32 + lane]);
        uint2 r2 = __ldg(&pin2[(int)i4.z * 32 + lane]);
        uint2 r3 = __ldg(&pin2[(int)i4.w * 32 + lane]);
        float2 a0 = __half22float2(*(__half2*)&r0.x), b0 = __half22float2(*(__half2*)&r0.y);
        float2 a1 = __half22float2(*(__half2*)&r1.x), b1 = __half22float2(*(__half2*)&r1.y);
        float2 a2 = __half22float2(*(__half2*)&r2.x), b2 = __half22float2(*(__half2*)&r2.y);
        float2 a3 = __half22float2(*(__half2*)&r3.x), b3 = __half22float2(*(__half2*)&r3.y);
        ax += a0.x + a1.x + a2.x + a3.x;
        ay += a0.y + a1.y + a2.y + a3.y;
        az += b0.x + b1.x + b2.x + b3.x;
        aw += b0.y + b1.y + b2.y + b3.y;
    }
    // tail
    for (; e < end; e++) {
        int s = g_csr[e];
        uint2 r = __ldg(&pin2[s * 32 + lane]);
        float2 a = __half22float2(*(__half2*)&r.x), b = __half22float2(*(__half2*)&r.y);
        ax += a.x; ay += a.y; az += b.x; aw += b.y;
    }

    float nd = g_norm[node];
    {
        __half2 lo = __floats2half2_rn(ax * nd, ay * nd);
        __half2 hi = __floats2half2_rn(az * nd, aw * nd);
        uint2 o; o.x = *(uint32_t*)&lo; o.y = *(uint32_t*)&hi;
        ((uint2*)hout)[node * 32 + lane] = o;
    }
    if (pout) {
        float n2 = nd * nd;
        __half2 lo = __floats2half2_rn(ax * n2, ay * n2);
        __half2 hi = __floats2half2_rn(az * n2, aw * n2);
        uint2 o; o.x = *(uint32_t*)&lo; o.y = *(uint32_t*)&hi;
        ((uint2*)pout)[node * 32 + lane] = o;
    }
}

// ---------------------------------------------------------------------------
// HMMA fp16 GEMM with cp.async double buffering.
// out[n][o] = bias[o] + sum_k x[n][k]*W[o][k]; x = [featH | h1H | h2H]
__device__ __forceinline__ uint32_t smem_u32(const void* p) {
    uint32_t a;
    asm("{ .reg .u64 t; cvta.to.shared.u64 t, %1; cvt.u32.u64 %0, t; }"
        : "=r"(a) : "l"(p));
    return a;
}
__device__ __forceinline__ uint32_t sw128(uint32_t off) {
    return off ^ ((off >> 3) & 0x70);
}

#define CHUNK_BYTES 16384   // 128 rows x 128B

__device__ __forceinline__ void gemm_load_chunk(uint32_t saA, uint32_t saB,
                                                int ch, int buf, int rowBase,
                                                int tid) {
    const __half* baseH = (ch < 2) ? g_featH : ((ch < 4) ? g_h1H : g_h2H);
    int koff = (ch & 1) * 64;
#pragma unroll
    for (int it = 0; it < 4; it++) {
        int idx = tid + it * 256;
        int r = idx >> 3;
        int j = idx & 7;
        int grow = rowBase + r;
        int inb = (grow < N_NODES);
        const __half* src = &baseH[(inb ? grow : 0) * D + koff + j * 8];
        int sz = inb ? 16 : 0;
        uint32_t dst = saA + buf * CHUNK_BYTES + sw128((uint32_t)(r * 128 + j * 16));
        asm volatile("cp.async.cg.shared.global [%0], [%1], 16, %2;"
                     :: "r"(dst), "l"(src), "r"(sz) : "memory");
    }
#pragma unroll
    for (int it = 0; it < 4; it++) {
        int idx = tid + it * 256;
        int r = idx >> 3;
        int j = idx & 7;
        const __half* src = &g_WH[r * FAN_IN + ch * 64 + j * 8];
        uint32_t dst = saB + buf * CHUNK_BYTES + sw128((uint32_t)(r * 128 + j * 16));
        asm volatile("cp.async.cg.shared.global [%0], [%1], 16;"
                     :: "r"(dst), "l"(src) : "memory");
    }
    asm volatile("cp.async.commit_group;" ::: "memory");
}

__global__ __launch_bounds__(256)
void gemm_hmma_kernel(const float* __restrict__ bias,
                      float* __restrict__ out) {
    extern __shared__ __align__(128) char smem[];
    char* smA = smem;                       // [2][16384]
    char* smB = smem + 2 * CHUNK_BYTES;     // [2][16384]

    int tid = threadIdx.x;
    int wid = tid >> 5;
    int lane = tid & 31;
    int warp_m = wid >> 2;
    int warp_n = wid & 3;
    int rowBase = blockIdx.x * 128;

    uint32_t saA = smem_u32(smA);
    uint32_t saB = smem_u32(smB);

    float acc[4][4][4];
#pragma unroll
    for (int i = 0; i < 4; i++)
#pragma unroll
        for (int j = 0; j < 4; j++)
#pragma unroll
            for (int q = 0; q < 4; q++) acc[i][j][q] = 0.f;

    gemm_load_chunk(saA, saB, 0, 0, rowBase, tid);

#pragma unroll
    for (int ch = 0; ch < 6; ch++) {
        int buf = ch & 1;
        if (ch < 5) gemm_load_chunk(saA, saB, ch + 1, buf ^ 1, rowBase, tid);
        if (ch < 5) asm volatile("cp.async.wait_group 1;" ::: "memory");
        else        asm volatile("cp.async.wait_group 0;" ::: "memory");
        __syncthreads();

        uint32_t sa = saA + buf * CHUNK_BYTES;
        uint32_t sb = saB + buf * CHUNK_BYTES;
#pragma unroll
        for (int kk = 0; kk < 4; kk++) {
            uint32_t afrag[4][4];
#pragma unroll
            for (int mi = 0; mi < 4; mi++) {
                int r = warp_m * 64 + mi * 16 + (lane & 15);
                uint32_t addr = sa + sw128((uint32_t)(r * 128 + kk * 32 + (lane >> 4) * 16));
                asm volatile(
                    "ldmatrix.sync.aligned.m8n8.x4.shared.b16 {%0,%1,%2,%3}, [%4];"
                    : "=r"(afrag[mi][0]), "=r"(afrag[mi][1]),
                      "=r"(afrag[mi][2]), "=r"(afrag[mi][3])
                    : "r"(addr));
            }
            uint32_t bfrag[4][2];
#pragma unroll
            for (int ni = 0; ni < 4; ni++) {
                int nr = warp_n * 32 + ni * 8 + (lane & 7);
                uint32_t addr = sb + sw128((uint32_t)(nr * 128 + kk * 32 + ((lane >> 3) & 1) * 16));
                asm volatile(
                    "ldmatrix.sync.aligned.m8n8.x2.shared.b16 {%0,%1}, [%2];"
                    : "=r"(bfrag[ni][0]), "=r"(bfrag[ni][1])
                    : "r"(addr));
            }
#pragma unroll
            for (int mi = 0; mi < 4; mi++)
#pragma unroll
                for (int ni = 0; ni < 4; ni++) {
                    asm volatile(
                        "mma.sync.aligned.m16n8k16.row.col.f32.f16.f16.f32 "
                        "{%0,%1,%2,%3}, {%4,%5,%6,%7}, {%8,%9}, {%0,%1,%2,%3};"
                        : "+f"(acc[mi][ni][0]), "+f"(acc[mi][ni][1]),
                          "+f"(acc[mi][ni][2]), "+f"(acc[mi][ni][3])
                        : "r"(afrag[mi][0]), "r"(afrag[mi][1]),
                          "r"(afrag[mi][2]), "r"(afrag[mi][3]),
                          "r"(bfrag[ni][0]), "r"(bfrag[ni][1]));
                }
        }
        __syncthreads();
    }

#pragma unroll
    for (int mi = 0; mi < 4; mi++) {
        int r0 = rowBase + warp_m * 64 + mi * 16 + (lane >> 2);
#pragma unroll
        for (int ni = 0; ni < 4; ni++) {
            int col = warp_n * 32 + ni * 8 + (lane & 3) * 2;
            float b0 = __ldg(&bias[col]);
            float b1 = __ldg(&bias[col + 1]);
            if (r0 < N_NODES) {
                *(float2*)&out[r0 * D + col] =
                    make_float2(acc[mi][ni][0] + b0, acc[mi][ni][1] + b1);
            }
            if (r0 + 8 < N_NODES) {
                *(float2*)&out[(r0 + 8) * D + col] =
                    make_float2(acc[mi][ni][2] + b0, acc[mi][ni][3] + b1);
            }
        }
    }
}

// ---------------------------------------------------------------------------
extern "C" void kernel_launch(void* const* d_in, const int* in_sizes, int n_in,
                              void* d_out, int out_size) {
    const float* feat = (const float*)d_in[0];
    const int*   src  = (const int*)d_in[1];
    const int*   dst  = (const int*)d_in[2];
    const float* W    = (const float*)d_in[3];
    const float* bias = (const float*)d_in[4];
    float* out = (float*)d_out;

    const int E = in_sizes[1];

    __half* p0;  cudaGetSymbolAddress((void**)&p0,  g_p0);
    __half* p1;  cudaGetSymbolAddress((void**)&p1,  g_p1);
    __half* h1H; cudaGetSymbolAddress((void**)&h1H, g_h1H);
    __half* h2H; cudaGetSymbolAddress((void**)&h2H, g_h2H);

    // 1. degrees
    deg_kernel<<<(E + 255) / 256, 256>>>(dst, E);
    // 2. fused scan
    scan_fused_kernel<<<SCAN_BLOCKS, 512>>>();
    // 3. CSR fill + converts + prescale + cleanup
    fill_convert_kernel<<<(N_NODES * D / 2 + 255) / 256, 256>>>(src, dst, feat, W, E);

    // 4-5. two SpMM hops (launch 4 = profiled slot)
    int gblocks = (N_NODES * 32 + 255) / 256;
    gather_kernel<<<gblocks, 256>>>(p0, h1H, p1);
    gather_kernel<<<gblocks, 256>>>(p1, h2H, (__half*)0);

    // 6. fused concat + linear, cp.async double-buffered HMMA
    cudaFuncSetAttribute(gemm_hmma_kernel,
                         cudaFuncAttributeMaxDynamicSharedMemorySize,
                         4 * CHUNK_BYTES);
    int gemmBlocks = (N_NODES + 127) / 128;
    gemm_hmma_kernel<<<gemmBlocks, 256, 4 * CHUNK_BYTES>>>(bias, out);
}

// round 11
// speedup vs baseline: 1.4620x; 1.0686x over previous
#include <cuda_runtime.h>
#include <cuda_fp16.h>
#include <math.h>
#include <stdint.h>

#define N_NODES 100000
#define D 128
#define FAN_IN 384
#define E_MAX 1600000
#define SCAN_BLOCKS ((N_NODES + 255) / 256)   // 391

// ---- scratch (__device__ globals; no allocations allowed) ----
__device__ __align__(16) __half g_featH[N_NODES * D];  // raw feat fp16 (GEMM)
__device__ __align__(16) __half g_p0[N_NODES * D];     // feat*norm (gather1 input)
__device__ __align__(16) __half g_p1[N_NODES * D];     // norm^2*q1 (gather2 input)
__device__ __align__(16) __half g_h1H[N_NODES * D];    // h1 (GEMM)
__device__ __align__(16) __half g_h2H[N_NODES * D];    // h2 (GEMM)
__device__ __align__(16) __half g_WH[FAN_IN * D];      // W fp16 [128][384]
__device__ float g_norm[N_NODES];
__device__ int   g_deg[N_NODES];            // zeroed at end of each run (+ static init)
__device__ int   g_row[N_NODES + 1];
__device__ int   g_cursor[N_NODES];
__device__ __align__(16) int g_csr[E_MAX];
__device__ volatile int g_agg[SCAN_BLOCKS];
__device__ volatile int g_boffp[SCAN_BLOCKS];

// ---------------------------------------------------------------------------
__device__ __forceinline__ int probe_is64(const int* dst32) {
    return (dst32[1] == 0 && dst32[2] == 1 && dst32[4] == 2) ? 1 : 0;
}
__device__ __forceinline__ int load_idx(const int* p, int e, int is64) {
    return is64 ? p[2 * e] : p[e];
}

// launch 1: degree histogram
__global__ void deg_kernel(const int* __restrict__ dst32, int E) {
    int is64 = probe_is64(dst32);
    int e = blockIdx.x * blockDim.x + threadIdx.x;
    if (e < E) atomicAdd(&g_deg[load_idx(dst32, e, is64)], 1);
}

// launch 2: fused single-pass scan (391 co-resident blocks, spin handshake)
__global__ __launch_bounds__(512)
void scan_fused_kernel() {
    __shared__ int sh[512];
    __shared__ int wsum[8];
    __shared__ int sh_total;
    __shared__ int sh_boff;
    int t = threadIdx.x;
    int b = blockIdx.x;
    int lane = t & 31, warp = t >> 5;
    int g = b * 256 + t;
    int v = (t < 256 && g < N_NODES) ? g_deg[g] : 0;

    int inc = v;
#pragma unroll
    for (int o = 1; o < 32; o <<= 1) {
        int u = __shfl_up_sync(0xffffffffu, inc, o);
        if (lane >= o) inc += u;
    }
    if (lane == 31 && warp < 8) wsum[warp] = inc;
    __syncthreads();
    if (t < 8) {
        int s = wsum[t];
        int si = s;
#pragma unroll
        for (int o = 1; o < 8; o <<= 1) {
            int u = __shfl_up_sync(0xffu, si, o);
            if (t >= o) si += u;
        }
        wsum[t] = si - s;
        if (t == 7) sh_total = si;
    }
    __syncthreads();

    if (t == 0) g_agg[b] = sh_total + 1;

    if (b == 0) {
        int a = 0;
        if (t < SCAN_BLOCKS) {
            while ((a = g_agg[t]) == 0) { }
            a -= 1;
        }
        sh[t] = a;
        __syncthreads();
        for (int off = 1; off < 512; off <<= 1) {
            int u = (t >= off) ? sh[t - off] : 0;
            __syncthreads();
            sh[t] += u;
            __syncthreads();
        }
        if (t < SCAN_BLOCKS)
            g_boffp[t] = ((t == 0) ? 0 : sh[t - 1]) + 1;
    }

    if (t == 0) {
        int bo;
        while ((bo = g_boffp[b]) == 0) { }
        sh_boff = bo - 1;
    }
    __syncthreads();

    if (t < 256 && g < N_NODES) {
        int row = sh_boff + wsum[warp] + inc - v;
        g_row[g] = row;
        g_cursor[g] = row;
        g_norm[g] = rsqrtf((float)v);
        if (g == N_NODES - 1) g_row[N_NODES] = row + v;
    }
}

// launch 3: CSR fill + featH + p0=feat*norm + WH + cleanup for next replay
__global__ void fill_convert_kernel(const int* __restrict__ src32,
                                    const int* __restrict__ dst32,
                                    const float* __restrict__ feat,
                                    const float* __restrict__ W, int E) {
    int i = blockIdx.x * blockDim.x + threadIdx.x;
    if (i < E) {
        int is64 = probe_is64(dst32);
        int tt = load_idx(dst32, i, is64);
        int s = load_idx(src32, i, is64);
        int pos = atomicAdd(&g_cursor[tt], 1);
        g_csr[pos] = s;
    }
    if (i < N_NODES * D / 2) {
        float nn = g_norm[i >> 6];
        float2 v = *(const float2*)&feat[i * 2];
        ((__half2*)g_featH)[i] = __floats2half2_rn(v.x, v.y);
        ((__half2*)g_p0)[i]    = __floats2half2_rn(v.x * nn, v.y * nn);
    }
    if (i < FAN_IN * D / 2) {
        float2 v = *(const float2*)&W[i * 2];
        ((__half2*)g_WH)[i] = __floats2half2_rn(v.x, v.y);
    }
    if (i < SCAN_BLOCKS) { g_agg[i] = 0; g_boffp[i] = 0; }
    if (i < N_NODES) g_deg[i] = 0;
}

// ---------------------------------------------------------------------------
// gather on prescaled input: q = sum_e pin[csr[e]];
// hout = norm*q (fp16); pout = norm^2*q (fp16) if non-null.
// Per 4-edge group: 6 HADD2 pairwise tree + single fp32 accumulate.
__global__ __launch_bounds__(256)
void gather_kernel(const __half* __restrict__ pin,
                   __half* __restrict__ hout,
                   __half* __restrict__ pout) {
    int node = (blockIdx.x * 256 + threadIdx.x) >> 5;
    int lane = threadIdx.x & 31;
    if (node >= N_NODES) return;
    int start = g_row[node];
    int end   = g_row[node + 1];

    const uint2* pin2 = (const uint2*)pin;
    float ax = 0.f, ay = 0.f, az = 0.f, aw = 0.f;

    int e = start;
    // scalar head until e is 4-aligned (g_csr is 16B aligned)
    while (e < end && (e & 3)) {
        int s = g_csr[e++];
        uint2 r = __ldg(&pin2[s * 32 + lane]);
        float2 a = __half22float2(*(__half2*)&r.x), b = __half22float2(*(__half2*)&r.y);
        ax += a.x; ay += a.y; az += b.x; aw += b.y;
    }
    // main: 4 edges per iter; fp16 pairwise tree (depth 2), fp32 accumulate
    for (; e + 4 <= end; e += 4) {
        uint4 i4 = *(const uint4*)&g_csr[e];
        uint2 r0 = __ldg(&pin2[(int)i4.x * 32 + lane]);
        uint2 r1 = __ldg(&pin2[(int)i4.y * 32 + lane]);
        uint2 r2 = __ldg(&pin2[(int)i4.z * 32 + lane]);
        uint2 r3 = __ldg(&pin2[(int)i4.w * 32 + lane]);
        __half2 s0 = __hadd2(*(__half2*)&r0.x, *(__half2*)&r1.x);
        __half2 s1 = __hadd2(*(__half2*)&r0.y, *(__half2*)&r1.y);
        __half2 s2 = __hadd2(*(__half2*)&r2.x, *(__half2*)&r3.x);
        __half2 s3 = __hadd2(*(__half2*)&r2.y, *(__half2*)&r3.y);
        __half2 t0 = __hadd2(s0, s2);
        __half2 t1 = __hadd2(s1, s3);
        float2 f0 = __half22float2(t0);
        float2 f1 = __half22float2(t1);
        ax += f0.x; ay += f0.y; az += f1.x; aw += f1.y;
    }
    // tail
    for (; e < end; e++) {
        int s = g_csr[e];
        uint2 r = __ldg(&pin2[s * 32 + lane]);
        float2 a = __half22float2(*(__half2*)&r.x), b = __half22float2(*(__half2*)&r.y);
        ax += a.x; ay += a.y; az += b.x; aw += b.y;
    }

    float nd = g_norm[node];
    {
        __half2 lo = __floats2half2_rn(ax * nd, ay * nd);
        __half2 hi = __floats2half2_rn(az * nd, aw * nd);
        uint2 o; o.x = *(uint32_t*)&lo; o.y = *(uint32_t*)&hi;
        ((uint2*)hout)[node * 32 + lane] = o;
    }
    if (pout) {
        float n2 = nd * nd;
        __half2 lo = __floats2half2_rn(ax * n2, ay * n2);
        __half2 hi = __floats2half2_rn(az * n2, aw * n2);
        uint2 o; o.x = *(uint32_t*)&lo; o.y = *(uint32_t*)&hi;
        ((uint2*)pout)[node * 32 + lane] = o;
    }
}

// ---------------------------------------------------------------------------
// HMMA fp16 GEMM with cp.async double buffering (measured-good R10 config).
__device__ __forceinline__ uint32_t smem_u32(const void* p) {
    uint32_t a;
    asm("{ .reg .u64 t; cvta.to.shared.u64 t, %1; cvt.u32.u64 %0, t; }"
        : "=r"(a) : "l"(p));
    return a;
}
__device__ __forceinline__ uint32_t sw128(uint32_t off) {
    return off ^ ((off >> 3) & 0x70);
}

#define CHUNK_BYTES 16384   // 128 rows x 128B

__device__ __forceinline__ void gemm_load_chunk(uint32_t saA, uint32_t saB,
                                                int ch, int buf, int rowBase,
                                                int tid) {
    const __half* baseH = (ch < 2) ? g_featH : ((ch < 4) ? g_h1H : g_h2H);
    int koff = (ch & 1) * 64;
#pragma unroll
    for (int it = 0; it < 4; it++) {
        int idx = tid + it * 256;
        int r = idx >> 3;
        int j = idx & 7;
        int grow = rowBase + r;
        int inb = (grow < N_NODES);
        const __half* src = &baseH[(inb ? grow : 0) * D + koff + j * 8];
        int sz = inb ? 16 : 0;
        uint32_t dst = saA + buf * CHUNK_BYTES + sw128((uint32_t)(r * 128 + j * 16));
        asm volatile("cp.async.cg.shared.global [%0], [%1], 16, %2;"
                     :: "r"(dst), "l"(src), "r"(sz) : "memory");
    }
#pragma unroll
    for (int it = 0; it < 4; it++) {
        int idx = tid + it * 256;
        int r = idx >> 3;
        int j = idx & 7;
        const __half* src = &g_WH[r * FAN_IN + ch * 64 + j * 8];
        uint32_t dst = saB + buf * CHUNK_BYTES + sw128((uint32_t)(r * 128 + j * 16));
        asm volatile("cp.async.cg.shared.global [%0], [%1], 16;"
                     :: "r"(dst), "l"(src) : "memory");
    }
    asm volatile("cp.async.commit_group;" ::: "memory");
}

__global__ __launch_bounds__(256)
void gemm_hmma_kernel(const float* __restrict__ bias,
                      float* __restrict__ out) {
    extern __shared__ __align__(128) char smem[];
    char* smA = smem;                       // [2][16384]
    char* smB = smem + 2 * CHUNK_BYTES;     // [2][16384]

    int tid = threadIdx.x;
    int wid = tid >> 5;
    int lane = tid & 31;
    int warp_m = wid >> 2;
    int warp_n = wid & 3;
    int rowBase = blockIdx.x * 128;

    uint32_t saA = smem_u32(smA);
    uint32_t saB = smem_u32(smB);

    float acc[4][4][4];
#pragma unroll
    for (int i = 0; i < 4; i++)
#pragma unroll
        for (int j = 0; j < 4; j++)
#pragma unroll
            for (int q = 0; q < 4; q++) acc[i][j][q] = 0.f;

    gemm_load_chunk(saA, saB, 0, 0, rowBase, tid);

#pragma unroll
    for (int ch = 0; ch < 6; ch++) {
        int buf = ch & 1;
        if (ch < 5) gemm_load_chunk(saA, saB, ch + 1, buf ^ 1, rowBase, tid);
        if (ch < 5) asm volatile("cp.async.wait_group 1;" ::: "memory");
        else        asm volatile("cp.async.wait_group 0;" ::: "memory");
        __syncthreads();

        uint32_t sa = saA + buf * CHUNK_BYTES;
        uint32_t sb = saB + buf * CHUNK_BYTES;
#pragma unroll
        for (int kk = 0; kk < 4; kk++) {
            uint32_t afrag[4][4];
#pragma unroll
            for (int mi = 0; mi < 4; mi++) {
                int r = warp_m * 64 + mi * 16 + (lane & 15);
                uint32_t addr = sa + sw128((uint32_t)(r * 128 + kk * 32 + (lane >> 4) * 16));
                asm volatile(
                    "ldmatrix.sync.aligned.m8n8.x4.shared.b16 {%0,%1,%2,%3}, [%4];"
                    : "=r"(afrag[mi][0]), "=r"(afrag[mi][1]),
                      "=r"(afrag[mi][2]), "=r"(afrag[mi][3])
                    : "r"(addr));
            }
            uint32_t bfrag[4][2];
#pragma unroll
            for (int ni = 0; ni < 4; ni++) {
                int nr = warp_n * 32 + ni * 8 + (lane & 7);
                uint32_t addr = sb + sw128((uint32_t)(nr * 128 + kk * 32 + ((lane >> 3) & 1) * 16));
                asm volatile(
                    "ldmatrix.sync.aligned.m8n8.x2.shared.b16 {%0,%1}, [%2];"
                    : "=r"(bfrag[ni][0]), "=r"(bfrag[ni][1])
                    : "r"(addr));
            }
#pragma unroll
            for (int mi = 0; mi < 4; mi++)
#pragma unroll
                for (int ni = 0; ni < 4; ni++) {
                    asm volatile(
                        "mma.sync.aligned.m16n8k16.row.col.f32.f16.f16.f32 "
                        "{%0,%1,%2,%3}, {%4,%5,%6,%7}, {%8,%9}, {%0,%1,%2,%3};"
                        : "+f"(acc[mi][ni][0]), "+f"(acc[mi][ni][1]),
                          "+f"(acc[mi][ni][2]), "+f"(acc[mi][ni][3])
                        : "r"(afrag[mi][0]), "r"(afrag[mi][1]),
                          "r"(afrag[mi][2]), "r"(afrag[mi][3]),
                          "r"(bfrag[ni][0]), "r"(bfrag[ni][1]));
                }
        }
        __syncthreads();
    }

#pragma unroll
    for (int mi = 0; mi < 4; mi++) {
        int r0 = rowBase + warp_m * 64 + mi * 16 + (lane >> 2);
#pragma unroll
        for (int ni = 0; ni < 4; ni++) {
            int col = warp_n * 32 + ni * 8 + (lane & 3) * 2;
            float b0 = __ldg(&bias[col]);
            float b1 = __ldg(&bias[col + 1]);
            if (r0 < N_NODES) {
                *(float2*)&out[r0 * D + col] =
                    make_float2(acc[mi][ni][0] + b0, acc[mi][ni][1] + b1);
            }
            if (r0 + 8 < N_NODES) {
                *(float2*)&out[(r0 + 8) * D + col] =
                    make_float2(acc[mi][ni][2] + b0, acc[mi][ni][3] + b1);
            }
        }
    }
}

// ---------------------------------------------------------------------------
extern "C" void kernel_launch(void* const* d_in, const int* in_sizes, int n_in,
                              void* d_out, int out_size) {
    const float* feat = (const float*)d_in[0];
    const int*   src  = (const int*)d_in[1];
    const int*   dst  = (const int*)d_in[2];
    const float* W    = (const float*)d_in[3];
    const float* bias = (const float*)d_in[4];
    float* out = (float*)d_out;

    const int E = in_sizes[1];

    __half* p0;  cudaGetSymbolAddress((void**)&p0,  g_p0);
    __half* p1;  cudaGetSymbolAddress((void**)&p1,  g_p1);
    __half* h1H; cudaGetSymbolAddress((void**)&h1H, g_h1H);
    __half* h2H; cudaGetSymbolAddress((void**)&h2H, g_h2H);

    // 1. degrees
    deg_kernel<<<(E + 255) / 256, 256>>>(dst, E);
    // 2. fused scan
    scan_fused_kernel<<<SCAN_BLOCKS, 512>>>();
    // 3. CSR fill + converts + prescale + cleanup
    fill_convert_kernel<<<(N_NODES * D / 2 + 255) / 256, 256>>>(src, dst, feat, W, E);

    // 4-5. two SpMM hops (launch 4 = profiled slot)
    int gblocks = (N_NODES * 32 + 255) / 256;
    gather_kernel<<<gblocks, 256>>>(p0, h1H, p1);
    gather_kernel<<<gblocks, 256>>>(p1, h2H, (__half*)0);

    // 6. fused concat + linear, cp.async double-buffered HMMA
    cudaFuncSetAttribute(gemm_hmma_kernel,
                         cudaFuncAttributeMaxDynamicSharedMemorySize,
                         4 * CHUNK_BYTES);
    int gemmBlocks = (N_NODES + 127) / 128;
    gemm_hmma_kernel<<<gemmBlocks, 256, 4 * CHUNK_BYTES>>>(bias, out);
}